// round 14
// baseline (speedup 1.0000x reference)
#include <cuda_runtime.h>
#include <cuda_fp16.h>
#include <cstdint>
#include <cstring>

// Problem constants
#define BB 2
#define QQ 10
#define CC 64
#define HH 256
#define WW 256
#define HWXY (HH * WW)            // 65536
#define KK 9
#define LL 64800                  // 180*360
#define NN (QQ * HWXY)            // 655360 per-b
#define BQ (BB * QQ)              // 20

// fp16 channel-last scratch: row n holds 64 halfs (128B) = 8 uint4
__device__ uint4  g_xt16[(size_t)BQ * HWXY * 8];     // 167.8 MB
// per-n channel stats (mean, max) in fp32
__device__ float2 g_stats[(size_t)BQ * HWXY];        // 10.5 MB
// per-(b,l) record: [n0,g0, n1,g1, ..., n8,g8, pad,pad]  (20 uints = 80B)
__device__ uint4  g_rec[(size_t)BB * LL * 5];        // 10.4 MB

__device__ __forceinline__ unsigned h2u(__half2 h) {
    unsigned u;
    memcpy(&u, &h, 4);
    return u;
}

// ---------------------------------------------------------------------------
// Kernel 1: per-bq transpose (C=64, HW) -> (HW, C=64) in fp16  +  stats.
// (Reverted to the measured-best smem-tile form: 88.3us, DRAM 65%.)
// block 256, tile 64(c) x 64(hw), grid (HW/64 = 1024, 1, BQ)
// ---------------------------------------------------------------------------
__global__ void __launch_bounds__(256)
transpose_stats_kernel(const float* __restrict__ x,
                       uint4* __restrict__ xt,
                       float2* __restrict__ stats)
{
    __shared__ __align__(16) float tile[CC][65];

    const int t   = threadIdx.x;
    const int hw0 = blockIdx.x * 64;
    const int bq  = blockIdx.z;
    const size_t inbase = (size_t)bq * CC * HWXY;

    // Load: 64 c-rows x 16 float4, coalesced 256B runs. Streaming (read-once).
    #pragma unroll
    for (int j = 0; j < 4; j++) {
        const int linear = t + 256 * j;
        const int c  = linear >> 4;
        const int f4 = linear & 15;
        const float4 v = __ldcs((const float4*)&x[inbase + (size_t)c * HWXY + hw0 + f4 * 4]);
        tile[c][f4 * 4 + 0] = v.x;
        tile[c][f4 * 4 + 1] = v.y;
        tile[c][f4 * 4 + 2] = v.z;
        tile[c][f4 * 4 + 3] = v.w;
    }
    __syncthreads();

    // Store: 64 n-rows x 8 uint4 (8 halfs each), perfectly coalesced 128B rows
    const size_t outbase = ((size_t)bq * HWXY + hw0) * 8;   // uint4 units
    #pragma unroll
    for (int j = 0; j < 2; j++) {
        const int s = t + 256 * j;
        const int n = s >> 3;
        const int g = s & 7;
        const int c0 = g * 8;
        uint4 u;
        u.x = h2u(__floats2half2_rn(tile[c0 + 0][n], tile[c0 + 1][n]));
        u.y = h2u(__floats2half2_rn(tile[c0 + 2][n], tile[c0 + 3][n]));
        u.z = h2u(__floats2half2_rn(tile[c0 + 4][n], tile[c0 + 5][n]));
        u.w = h2u(__floats2half2_rn(tile[c0 + 6][n], tile[c0 + 7][n]));
        xt[outbase + (size_t)n * 8 + g] = u;
    }

    // Stats: mean/max over c per hw. 4 lanes per hw, 16 c each + 2 shuffle steps.
    {
        const int hw = t >> 2;
        const int q  = t & 3;
        float s = tile[q * 16][hw];
        float m = s;
        #pragma unroll
        for (int i = 1; i < 16; i++) {
            const float v = tile[q * 16 + i][hw];
            s += v;
            m  = fmaxf(m, v);
        }
        s += __shfl_xor_sync(0xffffffffu, s, 1);
        m  = fmaxf(m, __shfl_xor_sync(0xffffffffu, m, 1));
        s += __shfl_xor_sync(0xffffffffu, s, 2);
        m  = fmaxf(m, __shfl_xor_sync(0xffffffffu, m, 2));
        if (q == 0)
            stats[(size_t)bq * HWXY + hw0 + hw] = make_float2(s * (1.0f / 64.0f), m);
    }
}

// ---------------------------------------------------------------------------
// Kernel 2: gate precompute. One thread per (b,l): read idx + stats, compute
// all 9 (1+sigmoid) gates, write interleaved record [n0,g0,...,n8,g8,pad2].
// grid ((BB*LL+255)/256), block 256
// ---------------------------------------------------------------------------
__global__ void __launch_bounds__(256)
gate_kernel(const float2* __restrict__ stats,
            const void* __restrict__ idx_raw,   // (64800,9) int32 OR int64
            const float* __restrict__ att_w,    // (9,2,9)
            const float* __restrict__ att_b,    // (9,)
            unsigned* __restrict__ rec)         // (BB*LL, 20) uints
{
    __shared__ float s_aw[KK * 2 * KK];
    __shared__ float s_ab[KK];
    const int tid = threadIdx.x;
    if (tid < KK * 2 * KK) s_aw[tid] = att_w[tid];
    if (tid < KK)          s_ab[tid] = att_b[tid];
    __syncthreads();

    const int gid = blockIdx.x * 256 + tid;
    if (gid >= BB * LL) return;
    const int b = gid / LL;
    const int l = gid - b * LL;

    // dtype sniff: int64 values < 2^31 have zero high words at odd 32-bit slots
    const int* __restrict__ i32 = (const int*)idx_raw;
    const bool is64 = (i32[1] | i32[3] | i32[5] | i32[7] |
                       i32[9] | i32[11] | i32[13] | i32[15]) == 0;

    int n[KK];
    #pragma unroll
    for (int k = 0; k < KK; k++) {
        const size_t pos = (size_t)l * KK + k;
        n[k] = is64 ? (int)((const long long*)idx_raw)[pos] : i32[pos];
    }

    float mn[KK], mx[KK];
    #pragma unroll
    for (int k = 0; k < KK; k++) {
        const float2 st = __ldg(&stats[(size_t)b * NN + n[k]]);
        mn[k] = st.x;
        mx[k] = st.y;
    }

    unsigned r[20];
    #pragma unroll
    for (int i = 0; i < KK; i++) {
        float z = s_ab[i];
        #pragma unroll
        for (int k = 0; k < KK; k++) {
            z = fmaf(mn[k], s_aw[i * 18 + k],     z);
            z = fmaf(mx[k], s_aw[i * 18 + 9 + k], z);
        }
        const float gte = 1.0f + 1.0f / (1.0f + __expf(-z));
        r[2 * i]     = (unsigned)n[i];
        r[2 * i + 1] = __float_as_uint(gte);
    }
    r[18] = 0; r[19] = 0;

    uint4* __restrict__ rec4 = (uint4*)rec;
    const size_t base = (size_t)gid * 5;
    #pragma unroll
    for (int q = 0; q < 5; q++)
        rec4[base + q] = make_uint4(r[q*4], r[q*4+1], r[q*4+2], r[q*4+3]);
}

// ---------------------------------------------------------------------------
// Kernel 3: gather + contraction. ZERO shuffles: block stages its 32 records
// in smem once; mainloop per l = 5 LDS.128 broadcast + 9 gather LDG + FMA.
// block 256 = 8 warps x 4 l = 32 consecutive l. grid: (LL/32 = 2025, BB)
// ---------------------------------------------------------------------------
__global__ void __launch_bounds__(256)
fused_kernel(const uint* __restrict__ xt16,      // half2 view of scratch
             const uint4* __restrict__ rec4,     // (BB*LL, 5) uint4
             const float* __restrict__ tc_w,     // (64,9)
             const float* __restrict__ tc_b,     // (64,)
             float* __restrict__ out)            // (B, 64, L)
{
    __shared__ __align__(16) uint4 s_rec[160];     // 32 records x 5 uint4
    __shared__ __align__(16) float s_out[CC][36];

    const int tid  = threadIdx.x;
    const int warp = tid >> 5;
    const int lane = tid & 31;
    const int b    = blockIdx.y;
    const int lblk = blockIdx.x * 32;
    const int c0   = lane * 2;

    // stage records (coalesced 2560B)
    {
        const size_t rbase = ((size_t)b * LL + lblk) * 5;
        if (tid < 160) s_rec[tid] = rec4[rbase + tid];
    }

    float w0[KK], w1[KK];
    #pragma unroll
    for (int k = 0; k < KK; k++) {
        w0[k] = __ldg(&tc_w[c0 * KK + k]);
        w1[k] = __ldg(&tc_w[(c0 + 1) * KK + k]);
    }
    const float bias0 = __ldg(&tc_b[c0]);
    const float bias1 = __ldg(&tc_b[c0 + 1]);

    __syncthreads();

    #pragma unroll
    for (int j = 0; j < 4; j++) {
        const int ll = warp * 4 + j;

        // 5 broadcast LDS.128: (n,gate) pairs for this l
        int   n[KK];
        float gt[KK];
        {
            const uint4 r0 = s_rec[ll * 5 + 0];
            const uint4 r1 = s_rec[ll * 5 + 1];
            const uint4 r2 = s_rec[ll * 5 + 2];
            const uint4 r3 = s_rec[ll * 5 + 3];
            const uint4 r4 = s_rec[ll * 5 + 4];
            n[0] = (int)r0.x;  gt[0] = __uint_as_float(r0.y);
            n[1] = (int)r0.z;  gt[1] = __uint_as_float(r0.w);
            n[2] = (int)r1.x;  gt[2] = __uint_as_float(r1.y);
            n[3] = (int)r1.z;  gt[3] = __uint_as_float(r1.w);
            n[4] = (int)r2.x;  gt[4] = __uint_as_float(r2.y);
            n[5] = (int)r2.z;  gt[5] = __uint_as_float(r2.w);
            n[6] = (int)r3.x;  gt[6] = __uint_as_float(r3.y);
            n[7] = (int)r3.z;  gt[7] = __uint_as_float(r3.w);
            n[8] = (int)r4.x;  gt[8] = __uint_as_float(r4.y);
        }

        // 9 coalesced 128B gathers (lane owns channels c0, c0+1)
        uint vu[KK];
        #pragma unroll
        for (int k = 0; k < KK; k++)
            vu[k] = xt16[((size_t)b * NN + (size_t)n[k]) * 32 + lane];

        float o0 = bias0, o1 = bias1;
        #pragma unroll
        for (int k = 0; k < KK; k++) {
            const float2 v = __half22float2(*(const __half2*)&vu[k]);
            o0 = fmaf(v.x * gt[k], w0[k], o0);
            o1 = fmaf(v.y * gt[k], w1[k], o1);
        }

        s_out[c0][ll]     = o0;
        s_out[c0 + 1][ll] = o1;
    }
    __syncthreads();

    // Coalesced output: 64 rows x 8 float4, full 128B lines
    #pragma unroll
    for (int s = tid; s < 512; s += 256) {
        const int c = s >> 3;
        const int q = s & 7;
        const float4 vv = *(const float4*)&s_out[c][q * 4];
        *(float4*)&out[((size_t)(b * CC + c)) * LL + lblk + q * 4] = vv;
    }
}

// ---------------------------------------------------------------------------
extern "C" void kernel_launch(void* const* d_in, const int* in_sizes, int n_in,
                              void* d_out, int out_size)
{
    const float* x     = (const float*)d_in[0];      // (20, 64, 256, 256)
    const void*  idx   = d_in[1];                    // (64800, 9) int32 or int64
    const float* att_w = (const float*)d_in[2];      // (9,2,9)
    const float* att_b = (const float*)d_in[3];      // (9,)
    const float* tc_w  = (const float*)d_in[4];      // (64,9)
    const float* tc_b  = (const float*)d_in[5];      // (64,)
    float*       out   = (float*)d_out;              // (2, 64, 180, 360)

    uint4* xt;  float2* stats;  uint4* rec;
    cudaGetSymbolAddress((void**)&xt, g_xt16);
    cudaGetSymbolAddress((void**)&stats, g_stats);
    cudaGetSymbolAddress((void**)&rec, g_rec);

    {
        dim3 grid(HWXY / 64, 1, BQ);
        transpose_stats_kernel<<<grid, 256>>>(x, xt, stats);
    }
    {
        dim3 grid((BB * LL + 255) / 256);
        gate_kernel<<<grid, 256>>>(stats, idx, att_w, att_b, (unsigned*)rec);
    }
    {
        dim3 grid(LL / 32, BB);
        fused_kernel<<<grid, 256>>>((const uint*)xt, (const uint4*)rec,
                                    tc_w, tc_b, out);
    }
}

// round 15
// speedup vs baseline: 1.0948x; 1.0948x over previous
#include <cuda_runtime.h>
#include <cuda_fp16.h>
#include <cstdint>
#include <cstring>

// Problem constants
#define BB 2
#define QQ 10
#define CC 64
#define HH 256
#define WW 256
#define HWXY (HH * WW)            // 65536
#define KK 9
#define LL 64800                  // 180*360
#define NN (QQ * HWXY)            // 655360 per-b
#define BQ (BB * QQ)              // 20

// fp16 channel-last scratch: row n holds 64 halfs (128B) = 8 uint4
__device__ uint4  g_xt16[(size_t)BQ * HWXY * 8];     // 167.8 MB
// per-n channel stats (mean, max) in fp32
__device__ float2 g_stats[(size_t)BQ * HWXY];        // 10.5 MB
// per-(b,l) record: [n0..n8, gatebits0..8, pad, pad]  (20 uints = 80B)
__device__ uint4  g_rec[(size_t)BB * LL * 5];        // 10.4 MB

__device__ __forceinline__ unsigned h2u(__half2 h) {
    unsigned u;
    memcpy(&u, &h, 4);
    return u;
}

// ---------------------------------------------------------------------------
// Kernel 1: per-bq transpose (C=64, HW) -> (HW, C=64) in fp16 + stats.
// Tile form (measured best) with stats fused into the pack phase: the 8
// column values each pack slot reads are reduced in-register and folded
// across the 8 consecutive g-lanes via shfl_xor — no stats smem re-read.
// block 256, tile 64(c) x 64(hw), grid (HW/64 = 1024, 1, BQ)
// ---------------------------------------------------------------------------
__global__ void __launch_bounds__(256)
transpose_stats_kernel(const float* __restrict__ x,
                       uint4* __restrict__ xt,
                       float2* __restrict__ stats)
{
    __shared__ __align__(16) float tile[CC][65];

    const int t   = threadIdx.x;
    const int hw0 = blockIdx.x * 64;
    const int bq  = blockIdx.z;
    const size_t inbase = (size_t)bq * CC * HWXY;

    // Load: 64 c-rows x 16 float4, coalesced 256B runs. Streaming (read-once).
    #pragma unroll
    for (int j = 0; j < 4; j++) {
        const int linear = t + 256 * j;
        const int c  = linear >> 4;
        const int f4 = linear & 15;
        const float4 v = __ldcs((const float4*)&x[inbase + (size_t)c * HWXY + hw0 + f4 * 4]);
        tile[c][f4 * 4 + 0] = v.x;
        tile[c][f4 * 4 + 1] = v.y;
        tile[c][f4 * 4 + 2] = v.z;
        tile[c][f4 * 4 + 3] = v.w;
    }
    __syncthreads();

    // Pack + store + stats: 64 n-rows x 8 uint4, coalesced 128B rows.
    // The 8 threads (g=0..7) of one n are consecutive lanes -> shfl reduce.
    const size_t outbase = ((size_t)bq * HWXY + hw0) * 8;   // uint4 units
    #pragma unroll
    for (int j = 0; j < 2; j++) {
        const int s = t + 256 * j;
        const int n = s >> 3;
        const int g = s & 7;
        const int c0 = g * 8;

        float f[8];
        #pragma unroll
        for (int i = 0; i < 8; i++) f[i] = tile[c0 + i][n];

        uint4 u;
        u.x = h2u(__floats2half2_rn(f[0], f[1]));
        u.y = h2u(__floats2half2_rn(f[2], f[3]));
        u.z = h2u(__floats2half2_rn(f[4], f[5]));
        u.w = h2u(__floats2half2_rn(f[6], f[7]));
        xt[outbase + (size_t)n * 8 + g] = u;

        // exact fp32 stats over the same 8 values, folded across g-lanes
        float ss = f[0], mm = f[0];
        #pragma unroll
        for (int i = 1; i < 8; i++) {
            ss += f[i];
            mm  = fmaxf(mm, f[i]);
        }
        #pragma unroll
        for (int o = 1; o < 8; o <<= 1) {
            ss += __shfl_xor_sync(0xffffffffu, ss, o);
            mm  = fmaxf(mm, __shfl_xor_sync(0xffffffffu, mm, o));
        }
        if (g == 0)
            stats[(size_t)bq * HWXY + hw0 + n] = make_float2(ss * (1.0f / 64.0f), mm);
    }
}

// ---------------------------------------------------------------------------
// Kernel 2: gate precompute (R9 form). One thread per (b,l): read idx + stats,
// compute all 9 (1+sigmoid) gates, write packed record [n0..8, gate0..8, pad2].
// grid ((BB*LL+255)/256), block 256
// ---------------------------------------------------------------------------
__global__ void __launch_bounds__(256)
gate_kernel(const float2* __restrict__ stats,
            const void* __restrict__ idx_raw,   // (64800,9) int32 OR int64
            const float* __restrict__ att_w,    // (9,2,9)
            const float* __restrict__ att_b,    // (9,)
            unsigned* __restrict__ rec)         // (BB*LL, 20) uints
{
    __shared__ float s_aw[KK * 2 * KK];
    __shared__ float s_ab[KK];
    const int tid = threadIdx.x;
    if (tid < KK * 2 * KK) s_aw[tid] = att_w[tid];
    if (tid < KK)          s_ab[tid] = att_b[tid];
    __syncthreads();

    const int gid = blockIdx.x * 256 + tid;
    if (gid >= BB * LL) return;
    const int b = gid / LL;
    const int l = gid - b * LL;

    // dtype sniff: int64 values < 2^31 have zero high words at odd 32-bit slots
    const int* __restrict__ i32 = (const int*)idx_raw;
    const bool is64 = (i32[1] | i32[3] | i32[5] | i32[7] |
                       i32[9] | i32[11] | i32[13] | i32[15]) == 0;

    int n[KK];
    #pragma unroll
    for (int k = 0; k < KK; k++) {
        const size_t pos = (size_t)l * KK + k;
        n[k] = is64 ? (int)((const long long*)idx_raw)[pos] : i32[pos];
    }

    float mn[KK], mx[KK];
    #pragma unroll
    for (int k = 0; k < KK; k++) {
        const float2 st = __ldg(&stats[(size_t)b * NN + n[k]]);
        mn[k] = st.x;
        mx[k] = st.y;
    }

    unsigned r[20];
    #pragma unroll
    for (int k = 0; k < KK; k++) r[k] = (unsigned)n[k];
    #pragma unroll
    for (int i = 0; i < KK; i++) {
        float z = s_ab[i];
        #pragma unroll
        for (int k = 0; k < KK; k++) {
            z = fmaf(mn[k], s_aw[i * 18 + k],     z);
            z = fmaf(mx[k], s_aw[i * 18 + 9 + k], z);
        }
        const float gte = 1.0f + 1.0f / (1.0f + __expf(-z));
        r[KK + i] = __float_as_uint(gte);
    }
    r[18] = 0; r[19] = 0;

    uint4* __restrict__ rec4 = (uint4*)rec;
    const size_t base = (size_t)gid * 5;
    #pragma unroll
    for (int q = 0; q < 5; q++)
        rec4[base + q] = make_uint4(r[q*4], r[q*4+1], r[q*4+2], r[q*4+3]);
}

// ---------------------------------------------------------------------------
// Kernel 3: gather + contraction (R9 form — measured best). Per l: one record
// load + 18 shfl + 9 gather LDG + 18 FMA. Warp-autonomous, no mainloop
// barriers. block 256 = 8 warps x 4 l = 32 consecutive l.
// grid: (LL/32 = 2025, BB)
// ---------------------------------------------------------------------------
__global__ void __launch_bounds__(256)
fused_kernel(const uint* __restrict__ xt16,      // half2 view of scratch
             const unsigned* __restrict__ rec,   // (BB*LL, 20)
             const float* __restrict__ tc_w,     // (64,9)
             const float* __restrict__ tc_b,     // (64,)
             float* __restrict__ out)            // (B, 64, L)
{
    __shared__ __align__(16) float s_out[CC][36];

    const int tid  = threadIdx.x;
    const int warp = tid >> 5;
    const int lane = tid & 31;
    const int b    = blockIdx.y;
    const int lblk = blockIdx.x * 32;
    const int c0   = lane * 2;

    float w0[KK], w1[KK];
    #pragma unroll
    for (int k = 0; k < KK; k++) {
        w0[k] = __ldg(&tc_w[c0 * KK + k]);
        w1[k] = __ldg(&tc_w[(c0 + 1) * KK + k]);
    }
    const float bias0 = __ldg(&tc_b[c0]);
    const float bias1 = __ldg(&tc_b[c0 + 1]);

    #pragma unroll
    for (int j = 0; j < 4; j++) {
        const int l  = lblk + warp * 4 + j;
        const int ll = warp * 4 + j;

        // one 72B record read: lanes 0..8 -> n, lanes 9..17 -> gate
        unsigned r = 0;
        if (lane < 18) r = rec[((size_t)b * LL + l) * 20 + lane];

        // broadcast indices, issue all gathers immediately (stay in flight)
        int n[KK];
        #pragma unroll
        for (int k = 0; k < KK; k++)
            n[k] = (int)__shfl_sync(0xffffffffu, r, k);

        uint vu[KK];
        #pragma unroll
        for (int k = 0; k < KK; k++)
            vu[k] = xt16[((size_t)b * NN + (size_t)n[k]) * 32 + lane];

        float o0 = bias0, o1 = bias1;
        #pragma unroll
        for (int k = 0; k < KK; k++) {
            const float sc = __uint_as_float(__shfl_sync(0xffffffffu, r, KK + k));
            const float2 v = __half22float2(*(const __half2*)&vu[k]);
            o0 = fmaf(v.x * sc, w0[k], o0);
            o1 = fmaf(v.y * sc, w1[k], o1);
        }

        s_out[c0][ll]     = o0;
        s_out[c0 + 1][ll] = o1;
    }
    __syncthreads();

    // Coalesced output: 64 rows x 8 float4, full 128B lines
    #pragma unroll
    for (int s = tid; s < 512; s += 256) {
        const int c = s >> 3;
        const int q = s & 7;
        const float4 vv = *(const float4*)&s_out[c][q * 4];
        *(float4*)&out[((size_t)(b * CC + c)) * LL + lblk + q * 4] = vv;
    }
}

// ---------------------------------------------------------------------------
extern "C" void kernel_launch(void* const* d_in, const int* in_sizes, int n_in,
                              void* d_out, int out_size)
{
    const float* x     = (const float*)d_in[0];      // (20, 64, 256, 256)
    const void*  idx   = d_in[1];                    // (64800, 9) int32 or int64
    const float* att_w = (const float*)d_in[2];      // (9,2,9)
    const float* att_b = (const float*)d_in[3];      // (9,)
    const float* tc_w  = (const float*)d_in[4];      // (64,9)
    const float* tc_b  = (const float*)d_in[5];      // (64,)
    float*       out   = (float*)d_out;              // (2, 64, 180, 360)

    uint4* xt;  float2* stats;  uint4* rec;
    cudaGetSymbolAddress((void**)&xt, g_xt16);
    cudaGetSymbolAddress((void**)&stats, g_stats);
    cudaGetSymbolAddress((void**)&rec, g_rec);

    {
        dim3 grid(HWXY / 64, 1, BQ);
        transpose_stats_kernel<<<grid, 256>>>(x, xt, stats);
    }
    {
        dim3 grid((BB * LL + 255) / 256);
        gate_kernel<<<grid, 256>>>(stats, idx, att_w, att_b, (unsigned*)rec);
    }
    {
        dim3 grid(LL / 32, BB);
        fused_kernel<<<grid, 256>>>((const uint*)xt, (const unsigned*)rec,
                                    tc_w, tc_b, out);
    }
}

// round 16
// speedup vs baseline: 1.1586x; 1.0583x over previous
#include <cuda_runtime.h>
#include <cuda_fp16.h>
#include <cstdint>
#include <cstring>

// Problem constants
#define BB 2
#define QQ 10
#define CC 64
#define HH 256
#define WW 256
#define HWXY (HH * WW)            // 65536
#define KK 9
#define LL 64800                  // 180*360
#define NN (QQ * HWXY)            // 655360 per-b
#define BQ (BB * QQ)              // 20

// fp16 channel-last scratch: row n holds 64 halfs (128B) = 8 uint4
__device__ uint4  g_xt16[(size_t)BQ * HWXY * 8];     // 167.8 MB
// per-n channel stats (mean, max) in fp32
__device__ float2 g_stats[(size_t)BQ * HWXY];        // 10.5 MB
// per-(b,l) record: [n0..n8, gatebits0..8, pad, pad]  (20 uints = 80B)
__device__ uint4  g_rec[(size_t)BB * LL * 5];        // 10.4 MB

__device__ __forceinline__ unsigned h2u(__half2 h) {
    unsigned u;
    memcpy(&u, &h, 4);
    return u;
}

// ---------------------------------------------------------------------------
// Kernel 1: per-bq transpose (C=64, HW) -> (HW, C=64) in fp16 + stats.
// (Frozen at R15 measured-best: 81.7us, DRAM 70%.)
// block 256, tile 64(c) x 64(hw), grid (HW/64 = 1024, 1, BQ)
// ---------------------------------------------------------------------------
__global__ void __launch_bounds__(256)
transpose_stats_kernel(const float* __restrict__ x,
                       uint4* __restrict__ xt,
                       float2* __restrict__ stats)
{
    __shared__ __align__(16) float tile[CC][65];

    const int t   = threadIdx.x;
    const int hw0 = blockIdx.x * 64;
    const int bq  = blockIdx.z;
    const size_t inbase = (size_t)bq * CC * HWXY;

    #pragma unroll
    for (int j = 0; j < 4; j++) {
        const int linear = t + 256 * j;
        const int c  = linear >> 4;
        const int f4 = linear & 15;
        const float4 v = __ldcs((const float4*)&x[inbase + (size_t)c * HWXY + hw0 + f4 * 4]);
        tile[c][f4 * 4 + 0] = v.x;
        tile[c][f4 * 4 + 1] = v.y;
        tile[c][f4 * 4 + 2] = v.z;
        tile[c][f4 * 4 + 3] = v.w;
    }
    __syncthreads();

    const size_t outbase = ((size_t)bq * HWXY + hw0) * 8;   // uint4 units
    #pragma unroll
    for (int j = 0; j < 2; j++) {
        const int s = t + 256 * j;
        const int n = s >> 3;
        const int g = s & 7;
        const int c0 = g * 8;

        float f[8];
        #pragma unroll
        for (int i = 0; i < 8; i++) f[i] = tile[c0 + i][n];

        uint4 u;
        u.x = h2u(__floats2half2_rn(f[0], f[1]));
        u.y = h2u(__floats2half2_rn(f[2], f[3]));
        u.z = h2u(__floats2half2_rn(f[4], f[5]));
        u.w = h2u(__floats2half2_rn(f[6], f[7]));
        xt[outbase + (size_t)n * 8 + g] = u;

        float ss = f[0], mm = f[0];
        #pragma unroll
        for (int i = 1; i < 8; i++) {
            ss += f[i];
            mm  = fmaxf(mm, f[i]);
        }
        #pragma unroll
        for (int o = 1; o < 8; o <<= 1) {
            ss += __shfl_xor_sync(0xffffffffu, ss, o);
            mm  = fmaxf(mm, __shfl_xor_sync(0xffffffffu, mm, o));
        }
        if (g == 0)
            stats[(size_t)bq * HWXY + hw0 + n] = make_float2(ss * (1.0f / 64.0f), mm);
    }
}

// ---------------------------------------------------------------------------
// Kernel 2: gate precompute (frozen R9/R15 form).
// grid ((BB*LL+255)/256), block 256
// ---------------------------------------------------------------------------
__global__ void __launch_bounds__(256)
gate_kernel(const float2* __restrict__ stats,
            const void* __restrict__ idx_raw,   // (64800,9) int32 OR int64
            const float* __restrict__ att_w,    // (9,2,9)
            const float* __restrict__ att_b,    // (9,)
            unsigned* __restrict__ rec)         // (BB*LL, 20) uints
{
    __shared__ float s_aw[KK * 2 * KK];
    __shared__ float s_ab[KK];
    const int tid = threadIdx.x;
    if (tid < KK * 2 * KK) s_aw[tid] = att_w[tid];
    if (tid < KK)          s_ab[tid] = att_b[tid];
    __syncthreads();

    const int gid = blockIdx.x * 256 + tid;
    if (gid >= BB * LL) return;
    const int b = gid / LL;
    const int l = gid - b * LL;

    // dtype sniff: int64 values < 2^31 have zero high words at odd 32-bit slots
    const int* __restrict__ i32 = (const int*)idx_raw;
    const bool is64 = (i32[1] | i32[3] | i32[5] | i32[7] |
                       i32[9] | i32[11] | i32[13] | i32[15]) == 0;

    int n[KK];
    #pragma unroll
    for (int k = 0; k < KK; k++) {
        const size_t pos = (size_t)l * KK + k;
        n[k] = is64 ? (int)((const long long*)idx_raw)[pos] : i32[pos];
    }

    float mn[KK], mx[KK];
    #pragma unroll
    for (int k = 0; k < KK; k++) {
        const float2 st = __ldg(&stats[(size_t)b * NN + n[k]]);
        mn[k] = st.x;
        mx[k] = st.y;
    }

    unsigned r[20];
    #pragma unroll
    for (int k = 0; k < KK; k++) r[k] = (unsigned)n[k];
    #pragma unroll
    for (int i = 0; i < KK; i++) {
        float z = s_ab[i];
        #pragma unroll
        for (int k = 0; k < KK; k++) {
            z = fmaf(mn[k], s_aw[i * 18 + k],     z);
            z = fmaf(mx[k], s_aw[i * 18 + 9 + k], z);
        }
        const float gte = 1.0f + 1.0f / (1.0f + __expf(-z));
        r[KK + i] = __float_as_uint(gte);
    }
    r[18] = 0; r[19] = 0;

    uint4* __restrict__ rec4 = (uint4*)rec;
    const size_t base = (size_t)gid * 5;
    #pragma unroll
    for (int q = 0; q < 5; q++)
        rec4[base + q] = make_uint4(r[q*4], r[q*4+1], r[q*4+2], r[q*4+3]);
}

// ---------------------------------------------------------------------------
// Kernel 3: gather + contraction, MLP-batched. Per warp: load all 4 records,
// then issue ALL 36 gathers (in flight concurrently), then consume. No
// mainloop barriers. block 256 = 8 warps x 4 l = 32 consecutive l.
// grid: (LL/32 = 2025, BB)
// ---------------------------------------------------------------------------
__global__ void __launch_bounds__(256)
fused_kernel(const uint* __restrict__ xt16,      // half2 view of scratch
             const unsigned* __restrict__ rec,   // (BB*LL, 20)
             const float* __restrict__ tc_w,     // (64,9)
             const float* __restrict__ tc_b,     // (64,)
             float* __restrict__ out)            // (B, 64, L)
{
    __shared__ __align__(16) float s_out[CC][36];

    const int tid  = threadIdx.x;
    const int warp = tid >> 5;
    const int lane = tid & 31;
    const int b    = blockIdx.y;
    const int lblk = blockIdx.x * 32;
    const int c0   = lane * 2;
    const int l0   = lblk + warp * 4;

    // Phase 1: all 4 record loads in flight (L2-resident, ~260cyc)
    unsigned r[4];
    #pragma unroll
    for (int j = 0; j < 4; j++) {
        r[j] = 0;
        if (lane < 18) r[j] = rec[((size_t)b * LL + (l0 + j)) * 20 + lane];
    }

    float w0[KK], w1[KK];
    #pragma unroll
    for (int k = 0; k < KK; k++) {
        w0[k] = __ldg(&tc_w[c0 * KK + k]);
        w1[k] = __ldg(&tc_w[(c0 + 1) * KK + k]);
    }
    const float bias0 = __ldg(&tc_b[c0]);
    const float bias1 = __ldg(&tc_b[c0 + 1]);

    // Phase 2: extract indices, issue all 36 gathers (MLP ~36)
    uint vu[4][KK];
    const size_t gbase = (size_t)b * NN * 32 + lane;
    #pragma unroll
    for (int j = 0; j < 4; j++) {
        #pragma unroll
        for (int k = 0; k < KK; k++) {
            const int n = (int)__shfl_sync(0xffffffffu, r[j], k);
            vu[j][k] = xt16[gbase + (size_t)n * 32];
        }
    }

    // Phase 3: gates + contraction + staged store
    #pragma unroll
    for (int j = 0; j < 4; j++) {
        float o0 = bias0, o1 = bias1;
        #pragma unroll
        for (int k = 0; k < KK; k++) {
            const float sc = __uint_as_float(__shfl_sync(0xffffffffu, r[j], KK + k));
            const float2 v = __half22float2(*(const __half2*)&vu[j][k]);
            o0 = fmaf(v.x * sc, w0[k], o0);
            o1 = fmaf(v.y * sc, w1[k], o1);
        }
        const int ll = warp * 4 + j;
        s_out[c0][ll]     = o0;
        s_out[c0 + 1][ll] = o1;
    }
    __syncthreads();

    // Coalesced output: 64 rows x 8 float4, full 128B lines
    #pragma unroll
    for (int s = tid; s < 512; s += 256) {
        const int c = s >> 3;
        const int q = s & 7;
        const float4 vv = *(const float4*)&s_out[c][q * 4];
        *(float4*)&out[((size_t)(b * CC + c)) * LL + lblk + q * 4] = vv;
    }
}

// ---------------------------------------------------------------------------
extern "C" void kernel_launch(void* const* d_in, const int* in_sizes, int n_in,
                              void* d_out, int out_size)
{
    const float* x     = (const float*)d_in[0];      // (20, 64, 256, 256)
    const void*  idx   = d_in[1];                    // (64800, 9) int32 or int64
    const float* att_w = (const float*)d_in[2];      // (9,2,9)
    const float* att_b = (const float*)d_in[3];      // (9,)
    const float* tc_w  = (const float*)d_in[4];      // (64,9)
    const float* tc_b  = (const float*)d_in[5];      // (64,)
    float*       out   = (float*)d_out;              // (2, 64, 180, 360)

    uint4* xt;  float2* stats;  uint4* rec;
    cudaGetSymbolAddress((void**)&xt, g_xt16);
    cudaGetSymbolAddress((void**)&stats, g_stats);
    cudaGetSymbolAddress((void**)&rec, g_rec);

    {
        dim3 grid(HWXY / 64, 1, BQ);
        transpose_stats_kernel<<<grid, 256>>>(x, xt, stats);
    }
    {
        dim3 grid((BB * LL + 255) / 256);
        gate_kernel<<<grid, 256>>>(stats, idx, att_w, att_b, (unsigned*)rec);
    }
    {
        dim3 grid(LL / 32, BB);
        fused_kernel<<<grid, 256>>>((const uint*)xt, (const unsigned*)rec,
                                    tc_w, tc_b, out);
    }
}

// round 17
// speedup vs baseline: 1.1838x; 1.0218x over previous
#include <cuda_runtime.h>
#include <cuda_fp16.h>
#include <cstdint>
#include <cstring>

// Problem constants
#define BB 2
#define QQ 10
#define CC 64
#define HH 256
#define WW 256
#define HWXY (HH * WW)            // 65536
#define KK 9
#define LL 64800                  // 180*360
#define NN (QQ * HWXY)            // 655360 per-b
#define BQ (BB * QQ)              // 20
#define LPW 6                     // l per warp (54 gathers in flight ~ MLP cap)
#define LBLK (8 * LPW)            // 48 l per block

// fp16 channel-last scratch: row n holds 64 halfs (128B) = 8 uint4
__device__ uint4  g_xt16[(size_t)BQ * HWXY * 8];     // 167.8 MB
// per-n channel stats (mean, max) in fp32
__device__ float2 g_stats[(size_t)BQ * HWXY];        // 10.5 MB
// per-(b,l) record: [n0..n8, gatebits0..8, pad, pad]  (20 uints = 80B)
__device__ uint4  g_rec[(size_t)BB * LL * 5];        // 10.4 MB

__device__ __forceinline__ unsigned h2u(__half2 h) {
    unsigned u;
    memcpy(&u, &h, 4);
    return u;
}

// ---------------------------------------------------------------------------
// Kernel 1: per-bq transpose (C=64, HW) -> (HW, C=64) in fp16 + stats.
// (Frozen at R15/R16 measured-best.)
// block 256, tile 64(c) x 64(hw), grid (HW/64 = 1024, 1, BQ)
// ---------------------------------------------------------------------------
__global__ void __launch_bounds__(256)
transpose_stats_kernel(const float* __restrict__ x,
                       uint4* __restrict__ xt,
                       float2* __restrict__ stats)
{
    __shared__ __align__(16) float tile[CC][65];

    const int t   = threadIdx.x;
    const int hw0 = blockIdx.x * 64;
    const int bq  = blockIdx.z;
    const size_t inbase = (size_t)bq * CC * HWXY;

    #pragma unroll
    for (int j = 0; j < 4; j++) {
        const int linear = t + 256 * j;
        const int c  = linear >> 4;
        const int f4 = linear & 15;
        const float4 v = __ldcs((const float4*)&x[inbase + (size_t)c * HWXY + hw0 + f4 * 4]);
        tile[c][f4 * 4 + 0] = v.x;
        tile[c][f4 * 4 + 1] = v.y;
        tile[c][f4 * 4 + 2] = v.z;
        tile[c][f4 * 4 + 3] = v.w;
    }
    __syncthreads();

    const size_t outbase = ((size_t)bq * HWXY + hw0) * 8;   // uint4 units
    #pragma unroll
    for (int j = 0; j < 2; j++) {
        const int s = t + 256 * j;
        const int n = s >> 3;
        const int g = s & 7;
        const int c0 = g * 8;

        float f[8];
        #pragma unroll
        for (int i = 0; i < 8; i++) f[i] = tile[c0 + i][n];

        uint4 u;
        u.x = h2u(__floats2half2_rn(f[0], f[1]));
        u.y = h2u(__floats2half2_rn(f[2], f[3]));
        u.z = h2u(__floats2half2_rn(f[4], f[5]));
        u.w = h2u(__floats2half2_rn(f[6], f[7]));
        xt[outbase + (size_t)n * 8 + g] = u;

        float ss = f[0], mm = f[0];
        #pragma unroll
        for (int i = 1; i < 8; i++) {
            ss += f[i];
            mm  = fmaxf(mm, f[i]);
        }
        #pragma unroll
        for (int o = 1; o < 8; o <<= 1) {
            ss += __shfl_xor_sync(0xffffffffu, ss, o);
            mm  = fmaxf(mm, __shfl_xor_sync(0xffffffffu, mm, o));
        }
        if (g == 0)
            stats[(size_t)bq * HWXY + hw0 + n] = make_float2(ss * (1.0f / 64.0f), mm);
    }
}

// ---------------------------------------------------------------------------
// Kernel 2: gate precompute (frozen).
// grid ((BB*LL+255)/256), block 256
// ---------------------------------------------------------------------------
__global__ void __launch_bounds__(256)
gate_kernel(const float2* __restrict__ stats,
            const void* __restrict__ idx_raw,   // (64800,9) int32 OR int64
            const float* __restrict__ att_w,    // (9,2,9)
            const float* __restrict__ att_b,    // (9,)
            unsigned* __restrict__ rec)         // (BB*LL, 20) uints
{
    __shared__ float s_aw[KK * 2 * KK];
    __shared__ float s_ab[KK];
    const int tid = threadIdx.x;
    if (tid < KK * 2 * KK) s_aw[tid] = att_w[tid];
    if (tid < KK)          s_ab[tid] = att_b[tid];
    __syncthreads();

    const int gid = blockIdx.x * 256 + tid;
    if (gid >= BB * LL) return;
    const int b = gid / LL;
    const int l = gid - b * LL;

    // dtype sniff: int64 values < 2^31 have zero high words at odd 32-bit slots
    const int* __restrict__ i32 = (const int*)idx_raw;
    const bool is64 = (i32[1] | i32[3] | i32[5] | i32[7] |
                       i32[9] | i32[11] | i32[13] | i32[15]) == 0;

    int n[KK];
    #pragma unroll
    for (int k = 0; k < KK; k++) {
        const size_t pos = (size_t)l * KK + k;
        n[k] = is64 ? (int)((const long long*)idx_raw)[pos] : i32[pos];
    }

    float mn[KK], mx[KK];
    #pragma unroll
    for (int k = 0; k < KK; k++) {
        const float2 st = __ldg(&stats[(size_t)b * NN + n[k]]);
        mn[k] = st.x;
        mx[k] = st.y;
    }

    unsigned r[20];
    #pragma unroll
    for (int k = 0; k < KK; k++) r[k] = (unsigned)n[k];
    #pragma unroll
    for (int i = 0; i < KK; i++) {
        float z = s_ab[i];
        #pragma unroll
        for (int k = 0; k < KK; k++) {
            z = fmaf(mn[k], s_aw[i * 18 + k],     z);
            z = fmaf(mx[k], s_aw[i * 18 + 9 + k], z);
        }
        const float gte = 1.0f + 1.0f / (1.0f + __expf(-z));
        r[KK + i] = __float_as_uint(gte);
    }
    r[18] = 0; r[19] = 0;

    uint4* __restrict__ rec4 = (uint4*)rec;
    const size_t base = (size_t)gid * 5;
    #pragma unroll
    for (int q = 0; q < 5; q++)
        rec4[base + q] = make_uint4(r[q*4], r[q*4+1], r[q*4+2], r[q*4+3]);
}

// ---------------------------------------------------------------------------
// Kernel 3: gather + contraction, MLP at the per-warp cap. Per warp: 6
// record loads, then ALL 54 gathers in flight, then consume. No mainloop
// barriers. block 256 = 8 warps x 6 l = 48 consecutive l.
// grid: (LL/48 = 1350, BB)
// ---------------------------------------------------------------------------
__global__ void __launch_bounds__(256)
fused_kernel(const uint* __restrict__ xt16,      // half2 view of scratch
             const unsigned* __restrict__ rec,   // (BB*LL, 20)
             const float* __restrict__ tc_w,     // (64,9)
             const float* __restrict__ tc_b,     // (64,)
             float* __restrict__ out)            // (B, 64, L)
{
    // row stride 52: mainloop STS banks = 8*lane (conflict-free);
    // epilogue LDS.128 quads near-linear in s (<=2-way).
    __shared__ __align__(16) float s_out[CC][52];

    const int tid  = threadIdx.x;
    const int warp = tid >> 5;
    const int lane = tid & 31;
    const int b    = blockIdx.y;
    const int lblk = blockIdx.x * LBLK;
    const int c0   = lane * 2;
    const int l0   = lblk + warp * LPW;

    // Phase 1: all 6 record loads in flight (L2-resident)
    unsigned r[LPW];
    #pragma unroll
    for (int j = 0; j < LPW; j++) {
        r[j] = 0;
        if (lane < 18) r[j] = rec[((size_t)b * LL + (l0 + j)) * 20 + lane];
    }

    float w0[KK], w1[KK];
    #pragma unroll
    for (int k = 0; k < KK; k++) {
        w0[k] = __ldg(&tc_w[c0 * KK + k]);
        w1[k] = __ldg(&tc_w[(c0 + 1) * KK + k]);
    }
    const float bias0 = __ldg(&tc_b[c0]);
    const float bias1 = __ldg(&tc_b[c0 + 1]);

    // Phase 2: extract indices, issue all 54 gathers (MLP ~54 = cap)
    uint vu[LPW][KK];
    const size_t gbase = (size_t)b * NN * 32 + lane;
    #pragma unroll
    for (int j = 0; j < LPW; j++) {
        #pragma unroll
        for (int k = 0; k < KK; k++) {
            const int n = (int)__shfl_sync(0xffffffffu, r[j], k);
            vu[j][k] = xt16[gbase + (size_t)n * 32];
        }
    }

    // Phase 3: gates + contraction + staged store
    #pragma unroll
    for (int j = 0; j < LPW; j++) {
        float o0 = bias0, o1 = bias1;
        #pragma unroll
        for (int k = 0; k < KK; k++) {
            const float sc = __uint_as_float(__shfl_sync(0xffffffffu, r[j], KK + k));
            const float2 v = __half22float2(*(const __half2*)&vu[j][k]);
            o0 = fmaf(v.x * sc, w0[k], o0);
            o1 = fmaf(v.y * sc, w1[k], o1);
        }
        const int ll = warp * LPW + j;
        s_out[c0][ll]     = o0;
        s_out[c0 + 1][ll] = o1;
    }
    __syncthreads();

    // Coalesced output: 64 rows x 12 float4 (48 floats), full 128B lines
    #pragma unroll
    for (int s = tid; s < CC * (LBLK / 4); s += 256) {
        const int c = s / (LBLK / 4);
        const int q = s - c * (LBLK / 4);
        const float4 vv = *(const float4*)&s_out[c][q * 4];
        *(float4*)&out[((size_t)(b * CC + c)) * LL + lblk + q * 4] = vv;
    }
}

// ---------------------------------------------------------------------------
extern "C" void kernel_launch(void* const* d_in, const int* in_sizes, int n_in,
                              void* d_out, int out_size)
{
    const float* x     = (const float*)d_in[0];      // (20, 64, 256, 256)
    const void*  idx   = d_in[1];                    // (64800, 9) int32 or int64
    const float* att_w = (const float*)d_in[2];      // (9,2,9)
    const float* att_b = (const float*)d_in[3];      // (9,)
    const float* tc_w  = (const float*)d_in[4];      // (64,9)
    const float* tc_b  = (const float*)d_in[5];      // (64,)
    float*       out   = (float*)d_out;              // (2, 64, 180, 360)

    uint4* xt;  float2* stats;  uint4* rec;
    cudaGetSymbolAddress((void**)&xt, g_xt16);
    cudaGetSymbolAddress((void**)&stats, g_stats);
    cudaGetSymbolAddress((void**)&rec, g_rec);

    {
        dim3 grid(HWXY / 64, 1, BQ);
        transpose_stats_kernel<<<grid, 256>>>(x, xt, stats);
    }
    {
        dim3 grid((BB * LL + 255) / 256);
        gate_kernel<<<grid, 256>>>(stats, idx, att_w, att_b, (unsigned*)rec);
    }
    {
        dim3 grid(LL / LBLK, BB);
        fused_kernel<<<grid, 256>>>((const uint*)xt, (const unsigned*)rec,
                                    tc_w, tc_b, out);
    }
}